// round 3
// baseline (speedup 1.0000x reference)
#include <cuda_runtime.h>

typedef unsigned long long u64;

#define R_ROWS 264384          // B*L*J = 64*243*17
#define NCOPY  256             // striped copies of BN accumulators
#define MBLKS  ((R_ROWS + 127) / 128)   // 2066

// ---------------- scratch (device globals: no allocations allowed) ----------
__device__ float g_t[(long long)R_ROWS * 256];    // t = x@WcT + bc, later hn
__device__ float g_h[(long long)R_ROWS * 256];    // h = relu(adj @ t)
__device__ float g_mid[(long long)R_ROWS * 512];  // MLP hidden
__device__ float g_WcT[256 * 256];                // (w1+w2)^T  [d][o]
__device__ float g_W1T[256 * 512];                // mlp_w1^T   [o][h]
__device__ float g_W2T[512 * 256];                // mlp_w2^T   [h][o]
__device__ float g_bc[256];                       // b1+b2
__device__ float g_stats[NCOPY * 512];            // per-copy [sum(256) | sumsq(256)]
__device__ float g_sc[256];                       // BN scale  = rstd*gamma
__device__ float g_tsh[256];                      // BN shift  = beta - mu*scale

// ---------------- packed f32x2 helpers (FFMA2: full-rate fp32 on sm_103a) ---
__device__ __forceinline__ u64 ffma2(u64 a, u64 b, u64 c) {
    u64 d;
    asm("fma.rn.f32x2 %0, %1, %2, %3;" : "=l"(d) : "l"(a), "l"(b), "l"(c));
    return d;
}
__device__ __forceinline__ u64 dup2(float x) {
    u64 d;
    asm("mov.b64 %0, {%1, %1};" : "=l"(d) : "f"(x));
    return d;
}

// ---------------- K0: weight prep + stats zeroing ----------------------------
__global__ __launch_bounds__(256) void k_prep(
        const float* __restrict__ w1, const float* __restrict__ b1,
        const float* __restrict__ w2, const float* __restrict__ b2,
        const float* __restrict__ mw1, const float* __restrict__ mw2) {
    int i = blockIdx.x * 256 + threadIdx.x;          // exactly 0..131071
    // W1T[o][h] = mlp_w1[h][o]   (256x512)
    g_W1T[i] = mw1[(i & 511) * 256 + (i >> 9)];
    // W2T[h][o] = mlp_w2[o][h]   (512x256)
    g_W2T[i] = mw2[(i & 255) * 512 + (i >> 8)];
    g_stats[i] = 0.f;
    if (i < 256 * 256) {
        // WcT[d][o] = w1[o][d] + w2[o][d]
        g_WcT[i] = w1[(i & 255) * 256 + (i >> 8)] + w2[(i & 255) * 256 + (i >> 8)];
    }
    if (i < 256) g_bc[i] = b1[i] + b2[i];
}

// ---------------- generic SGEMM: C[M,N] = A[M,K] @ B[K,N] + bias (opt relu) --
// CTA tile 128x64, BK=16, 256 threads, 8(M)x4(N) micro-tile via f32x2 pairs.
template <bool RELU>
__global__ __launch_bounds__(256) void k_gemm(const float* __restrict__ A,
                                              const float* __restrict__ B,
                                              const float* __restrict__ bias,
                                              float* __restrict__ C,
                                              int M, int N, int K) {
    const int BM = 128, BN = 64, BK = 16;
    __shared__ float As[BK][BM + 4];   // transposed A tile
    __shared__ float Bs[BK][BN];
    int tid = threadIdx.x;
    int row0 = blockIdx.y * BM;
    int n0 = blockIdx.x * BN;
    int tx = tid & 15;          // col group (4 cols each)
    int ty = tid >> 4;          // row group (8 rows each)
    int ar = tid >> 2;          // A-load row (0..63, +64 second pass)
    int ac = (tid & 3) << 2;    // A-load col (float4)
    int bkr = tid >> 4;         // B-load k row
    int bcc = (tid & 15) << 2;  // B-load col (float4)

    u64 acc[4][4];
#pragma unroll
    for (int i = 0; i < 4; i++)
#pragma unroll
        for (int j = 0; j < 4; j++) acc[i][j] = 0ull;

    for (int k0 = 0; k0 < K; k0 += BK) {
#pragma unroll
        for (int p = 0; p < 2; p++) {
            int r = ar + p * 64;
            float4 v = make_float4(0.f, 0.f, 0.f, 0.f);
            if (row0 + r < M)
                v = *(const float4*)(A + (size_t)(row0 + r) * K + k0 + ac);
            As[ac + 0][r] = v.x;
            As[ac + 1][r] = v.y;
            As[ac + 2][r] = v.z;
            As[ac + 3][r] = v.w;
        }
        *(float4*)&Bs[bkr][bcc] =
            *(const float4*)(B + (size_t)(k0 + bkr) * N + n0 + bcc);
        __syncthreads();
#pragma unroll
        for (int kk = 0; kk < BK; kk++) {
            u64 a2[4];
#pragma unroll
            for (int i = 0; i < 4; i++)
                a2[i] = *(const u64*)&As[kk][ty * 8 + 2 * i];
            float4 bq = *(const float4*)&Bs[kk][tx * 4];
            u64 bd0 = dup2(bq.x), bd1 = dup2(bq.y), bd2 = dup2(bq.z), bd3 = dup2(bq.w);
#pragma unroll
            for (int i = 0; i < 4; i++) {
                acc[i][0] = ffma2(a2[i], bd0, acc[i][0]);
                acc[i][1] = ffma2(a2[i], bd1, acc[i][1]);
                acc[i][2] = ffma2(a2[i], bd2, acc[i][2]);
                acc[i][3] = ffma2(a2[i], bd3, acc[i][3]);
            }
        }
        __syncthreads();
    }

    float4 bv = *(const float4*)(bias + n0 + tx * 4);
#pragma unroll
    for (int i = 0; i < 4; i++) {
        float2 c0 = *(float2*)&acc[i][0];
        float2 c1 = *(float2*)&acc[i][1];
        float2 c2 = *(float2*)&acc[i][2];
        float2 c3 = *(float2*)&acc[i][3];
        float4 lo = make_float4(c0.x + bv.x, c1.x + bv.y, c2.x + bv.z, c3.x + bv.w);
        float4 hi = make_float4(c0.y + bv.x, c1.y + bv.y, c2.y + bv.z, c3.y + bv.w);
        if (RELU) {
            lo.x = fmaxf(lo.x, 0.f); lo.y = fmaxf(lo.y, 0.f);
            lo.z = fmaxf(lo.z, 0.f); lo.w = fmaxf(lo.w, 0.f);
            hi.x = fmaxf(hi.x, 0.f); hi.y = fmaxf(hi.y, 0.f);
            hi.z = fmaxf(hi.z, 0.f); hi.w = fmaxf(hi.w, 0.f);
        }
        int r = row0 + ty * 8 + 2 * i;
        if (r < M)
            *(float4*)(C + (size_t)r * N + n0 + tx * 4) = lo;
        if (r + 1 < M)
            *(float4*)(C + (size_t)(r + 1) * N + n0 + tx * 4) = hi;
    }
}

// ---------------- K2: per-frame adjacency mix + relu + BN partial stats ------
__global__ __launch_bounds__(256) void k_adj(const float* __restrict__ adj) {
    __shared__ float sadj[17 * 17];
    int f = blockIdx.x;
    int o = threadIdx.x;  // output channel
    for (int i = o; i < 289; i += 256) sadj[i] = adj[i];
    __syncthreads();
    const float* tp = g_t + (size_t)f * 17 * 256 + o;
    float v[17];
#pragma unroll
    for (int j = 0; j < 17; j++) v[j] = tp[(size_t)j * 256];
    float* hp = g_h + (size_t)f * 17 * 256 + o;
    float s = 0.f, s2 = 0.f;
#pragma unroll
    for (int i = 0; i < 17; i++) {
        float g = 0.f;
#pragma unroll
        for (int j = 0; j < 17; j++) g = fmaf(sadj[i * 17 + j], v[j], g);
        g = fmaxf(g, 0.f);
        hp[(size_t)i * 256] = g;
        s += g;
        s2 = fmaf(g, g, s2);
    }
    float* st = g_stats + (size_t)(blockIdx.x & (NCOPY - 1)) * 512;
    atomicAdd(st + o, s);
    atomicAdd(st + 256 + o, s2);
}

// ---------------- K3: finalize BN statistics ---------------------------------
__global__ __launch_bounds__(256) void k_finstats(const float* __restrict__ bg,
                                                  const float* __restrict__ bb) {
    int o = threadIdx.x;
    float s = 0.f, s2 = 0.f;
    for (int c = 0; c < NCOPY; c++) {
        s += g_stats[c * 512 + o];
        s2 += g_stats[c * 512 + 256 + o];
    }
    const float inv = 1.f / (float)R_ROWS;
    float mu = s * inv;
    float var = fmaxf(s2 * inv - mu * mu, 0.f);
    float rs = rsqrtf(var + 1e-5f);
    float sc = rs * bg[o];
    g_sc[o] = sc;
    g_tsh[o] = bb[o] - mu * sc;
}

// ---------------- K4: fused BN apply + LayerNorm (warp per row) → hn in g_t --
__global__ __launch_bounds__(256) void k_bnln(const float* __restrict__ lg,
                                              const float* __restrict__ lb) {
    int row = blockIdx.x * 8 + (threadIdx.x >> 5);
    int lane = threadIdx.x & 31;
    const float* hp = g_h + (size_t)row * 256;
    float v[8];
    float s = 0.f, s2 = 0.f;
#pragma unroll
    for (int i = 0; i < 8; i++) {
        int k = lane + 32 * i;
        float x = fmaf(hp[k], g_sc[k], g_tsh[k]);
        v[i] = x;
        s += x;
        s2 = fmaf(x, x, s2);
    }
#pragma unroll
    for (int off = 16; off; off >>= 1) {
        s += __shfl_xor_sync(0xffffffffu, s, off);
        s2 += __shfl_xor_sync(0xffffffffu, s2, off);
    }
    float mu = s * (1.f / 256.f);
    float var = fmaxf(s2 * (1.f / 256.f) - mu * mu, 0.f);
    float rs = rsqrtf(var + 1e-5f);
    float* op = g_t + (size_t)row * 256;
#pragma unroll
    for (int i = 0; i < 8; i++) {
        int k = lane + 32 * i;
        op[k] = fmaf((v[i] - mu) * rs, lg[k], lb[k]);
    }
}

// ---------------- host side --------------------------------------------------
extern "C" void kernel_launch(void* const* d_in, const int* in_sizes, int n_in,
                              void* d_out, int out_size) {
    (void)in_sizes; (void)n_in; (void)out_size;
    const float* x   = (const float*)d_in[0];
    const float* adj = (const float*)d_in[1];
    const float* w1  = (const float*)d_in[2];
    const float* b1  = (const float*)d_in[3];
    const float* w2  = (const float*)d_in[4];
    const float* b2  = (const float*)d_in[5];
    const float* bng = (const float*)d_in[6];
    const float* bnb = (const float*)d_in[7];
    const float* lng = (const float*)d_in[8];
    const float* lnb = (const float*)d_in[9];
    const float* mw1 = (const float*)d_in[10];
    const float* mb1 = (const float*)d_in[11];
    const float* mw2 = (const float*)d_in[12];
    const float* mb2 = (const float*)d_in[13];
    float* out = (float*)d_out;

    void *pt = 0, *pm = 0, *pWc = 0, *pW1 = 0, *pW2 = 0, *pbc = 0;
    cudaGetSymbolAddress(&pt, g_t);
    cudaGetSymbolAddress(&pm, g_mid);
    cudaGetSymbolAddress(&pWc, g_WcT);
    cudaGetSymbolAddress(&pW1, g_W1T);
    cudaGetSymbolAddress(&pW2, g_W2T);
    cudaGetSymbolAddress(&pbc, g_bc);

    k_prep<<<512, 256>>>(w1, b1, w2, b2, mw1, mw2);
    // t = x @ WcT + bc
    k_gemm<false><<<dim3(4, MBLKS), 256>>>(x, (const float*)pWc, (const float*)pbc,
                                           (float*)pt, R_ROWS, 256, 256);
    // h = relu(adj @ t) + BN partial stats
    k_adj<<<R_ROWS / 17, 256>>>(adj);
    k_finstats<<<1, 256>>>(bng, bnb);
    // hn (into g_t) = LN(BN(h))
    k_bnln<<<R_ROWS / 8, 256>>>(lng, lnb);
    // mid = relu(hn @ W1T + mb1)
    k_gemm<true><<<dim3(8, MBLKS), 256>>>((const float*)pt, (const float*)pW1, mb1,
                                          (float*)pm, R_ROWS, 512, 256);
    // out = mid @ W2T + mb2
    k_gemm<false><<<dim3(4, MBLKS), 256>>>((const float*)pm, (const float*)pW2, mb2,
                                           out, R_ROWS, 256, 512);
}

// round 6
// speedup vs baseline: 2.7131x; 2.7131x over previous
#include <cuda_runtime.h>
#include <cstdint>

#define R_ROWS 264384                    // B*L*J = 64*243*17
#define NCOPY  64                        // striped BN accumulator copies
#define MTILES ((R_ROWS + 127) / 128)    // 2066

// ---------------- scratch (device globals: no allocations allowed) ----------
__device__ float g_t[(long long)R_ROWS * 256];    // t = x@Wc^T + bc, later hn
__device__ float g_h[(long long)R_ROWS * 256];    // h = relu(adj-mix)
__device__ float g_mid[(long long)R_ROWS * 512];  // MLP hidden
__device__ float g_Wc[256 * 256];                 // rna(w1+w2)   [o][d] K-major
__device__ float g_W1r[512 * 256];                // rna(mlp_w1)  [h][o] K-major
__device__ float g_W2r[256 * 512];                // rna(mlp_w2)  [o][h] K-major
__device__ float g_bc[256];                       // b1+b2
__device__ float g_stats[NCOPY * 512];            // [sum(256)|sumsq(256)] per copy
__device__ float g_sc[256];                       // BN scale
__device__ float g_tsh[256];                      // BN shift

// ---------------- helpers ----------------------------------------------------
__device__ __forceinline__ uint32_t smem_u32(const void* p) {
    uint32_t a;
    asm("{ .reg .u64 t; cvta.to.shared.u64 t, %1; cvt.u32.u64 %0, t; }"
        : "=r"(a) : "l"(p));
    return a;
}
__device__ __forceinline__ float rna_tf32(float x) {
    float r;
    asm("cvt.rna.tf32.f32 %0, %1;" : "=f"(r) : "f"(x));
    return r;
}
__device__ __forceinline__ uint32_t rna_tf32_u(uint32_t x) {
    float r;
    asm("cvt.rna.tf32.f32 %0, %1;" : "=f"(r) : "f"(__uint_as_float(x)));
    return __float_as_uint(r);
}
__device__ __forceinline__ void mma_tf32(float* d, const uint32_t* a, const uint32_t* b) {
    asm volatile(
        "mma.sync.aligned.m16n8k8.row.col.f32.tf32.tf32.f32 "
        "{%0,%1,%2,%3}, {%4,%5,%6,%7}, {%8,%9}, {%0,%1,%2,%3};\n"
        : "+f"(d[0]), "+f"(d[1]), "+f"(d[2]), "+f"(d[3])
        : "r"(a[0]), "r"(a[1]), "r"(a[2]), "r"(a[3]), "r"(b[0]), "r"(b[1]));
}
__device__ __forceinline__ void cp16(uint32_t dst, const void* src) {
    asm volatile("cp.async.cg.shared.global [%0], [%1], 16;" :: "r"(dst), "l"(src));
}
__device__ __forceinline__ void cp16z(uint32_t dst, const void* src, unsigned pred16) {
    asm volatile("cp.async.cg.shared.global [%0], [%1], 16, %2;"
                 :: "r"(dst), "l"(src), "r"(pred16));
}

// ---------------- K0: weight prep (tf32-round all GEMM weights) --------------
__global__ __launch_bounds__(256) void k_prep(
        const float* __restrict__ w1, const float* __restrict__ b1,
        const float* __restrict__ w2, const float* __restrict__ b2,
        const float* __restrict__ mw1, const float* __restrict__ mw2) {
    int i = blockIdx.x * 256 + threadIdx.x;   // 0..131071
    g_W1r[i] = rna_tf32(mw1[i]);              // native [512,256] K-major
    g_W2r[i] = rna_tf32(mw2[i]);              // native [256,512] K-major
    if (i < 256 * 256) g_Wc[i] = rna_tf32(w1[i] + w2[i]);
    if (i < NCOPY * 512) g_stats[i] = 0.f;
    if (i < 256) g_bc[i] = b1[i] + b2[i];
}

// ---------- mma.sync tf32 GEMM: C[M,N] = A[M,K] @ Bw[N,K]^T + bias -----------
// CTA 128x128, BK=32, 256 thr (8 warps: 2M x 4N), warp tile 64x32.
// smem rows padded to 36 floats -> all fragment loads bank-conflict-free.
#define LDA 36
#define ABUF (128 * LDA * 4)              // 18432 B per stage

template <bool RELU, bool ROUND_A, bool ROUND_OUT>
__global__ __launch_bounds__(256, 2) void k_mma(
        const float* __restrict__ A, const float* __restrict__ Bw,
        const float* __restrict__ bias, float* __restrict__ C,
        int M, int N, int K) {
    extern __shared__ char dsm[];
    __shared__ float s_bias[128];

    const int tid = threadIdx.x;
    const int wid = tid >> 5, lane = tid & 31;
    const int wm = wid >> 2, wn = wid & 3;      // warp grid 2x4
    const int row0 = blockIdx.y * 128;
    const int n0 = blockIdx.x * 128;
    const int NC = K >> 5;

    const uint32_t sb = smem_u32(dsm);
    const uint32_t sA[2] = {sb, sb + ABUF};
    const uint32_t sB[2] = {sb + 2 * ABUF, sb + 3 * ABUF};

    if (tid < 128) s_bias[tid] = bias[n0 + tid];

    // chunk loader: 128 rows x 32 cols (8 x 16B segs per row), 1024 segs each
    auto load_chunk = [&](int ck, int buf) {
        const int k0 = ck << 5;
#pragma unroll
        for (int j = 0; j < 4; j++) {
            int id = tid + (j << 8);
            int r = id >> 3, seg = id & 7;
            int gr = row0 + r;
            const float* gp = A + (size_t)(gr < M ? gr : (M - 1)) * K + k0 + (seg << 2);
            cp16z(sA[buf] + (uint32_t)(r * LDA + (seg << 2)) * 4u, gp,
                  gr < M ? 16u : 0u);
        }
#pragma unroll
        for (int j = 0; j < 4; j++) {
            int id = tid + (j << 8);
            int r = id >> 3, seg = id & 7;
            const float* gp = Bw + (size_t)(n0 + r) * K + k0 + (seg << 2);
            cp16(sB[buf] + (uint32_t)(r * LDA + (seg << 2)) * 4u, gp);
        }
        asm volatile("cp.async.commit_group;" ::: "memory");
    };

    float acc[4][4][4];
#pragma unroll
    for (int i = 0; i < 4; i++)
#pragma unroll
        for (int j = 0; j < 4; j++)
#pragma unroll
            for (int r = 0; r < 4; r++) acc[i][j][r] = 0.f;

    load_chunk(0, 0);

    const int qr = lane >> 2, qc = lane & 3;    // quad row / col
    for (int c = 0; c < NC; c++) {
        const int cb = c & 1;
        if (c + 1 < NC) {
            load_chunk(c + 1, (c + 1) & 1);
            asm volatile("cp.async.wait_group 1;" ::: "memory");
        } else {
            asm volatile("cp.async.wait_group 0;" ::: "memory");
        }
        __syncthreads();

        const uint32_t bA = sA[cb] + ((wm * 64 + qr) * LDA + qc) * 4u;
        const uint32_t bB = sB[cb] + ((wn * 32 + qr) * LDA + qc) * 4u;
#pragma unroll
        for (int s = 0; s < 4; s++) {           // 4 k-steps of 8
            const uint32_t ks = s * 8 * 4u;
            uint32_t af[4][4], bf[4][2];
#pragma unroll
            for (int mt = 0; mt < 4; mt++) {
                uint32_t base = bA + ks + (uint32_t)(mt * 16 * LDA) * 4u;
                asm volatile("ld.shared.b32 %0, [%1];" : "=r"(af[mt][0]) : "r"(base));
                asm volatile("ld.shared.b32 %0, [%1];" : "=r"(af[mt][1]) : "r"(base + 8u * LDA * 4u));
                asm volatile("ld.shared.b32 %0, [%1];" : "=r"(af[mt][2]) : "r"(base + 16u));
                asm volatile("ld.shared.b32 %0, [%1];" : "=r"(af[mt][3]) : "r"(base + 8u * LDA * 4u + 16u));
                if (ROUND_A) {
#pragma unroll
                    for (int r = 0; r < 4; r++) af[mt][r] = rna_tf32_u(af[mt][r]);
                }
            }
#pragma unroll
            for (int nt = 0; nt < 4; nt++) {
                uint32_t base = bB + ks + (uint32_t)(nt * 8 * LDA) * 4u;
                asm volatile("ld.shared.b32 %0, [%1];" : "=r"(bf[nt][0]) : "r"(base));
                asm volatile("ld.shared.b32 %0, [%1];" : "=r"(bf[nt][1]) : "r"(base + 16u));
            }
#pragma unroll
            for (int mt = 0; mt < 4; mt++)
#pragma unroll
                for (int nt = 0; nt < 4; nt++)
                    mma_tf32(acc[mt][nt], af[mt], bf[nt]);
        }
        __syncthreads();
    }

    // epilogue: bias (+relu) (+tf32 round), float2 stores
#pragma unroll
    for (int mt = 0; mt < 4; mt++) {
        int r0 = row0 + wm * 64 + mt * 16 + qr;
#pragma unroll
        for (int nt = 0; nt < 4; nt++) {
            int cc = wn * 32 + nt * 8 + qc * 2;
            float b0 = s_bias[cc], b1 = s_bias[cc + 1];
            float v0 = acc[mt][nt][0] + b0, v1 = acc[mt][nt][1] + b1;
            float v2 = acc[mt][nt][2] + b0, v3 = acc[mt][nt][3] + b1;
            if (RELU) {
                v0 = fmaxf(v0, 0.f); v1 = fmaxf(v1, 0.f);
                v2 = fmaxf(v2, 0.f); v3 = fmaxf(v3, 0.f);
            }
            if (ROUND_OUT) {
                v0 = rna_tf32(v0); v1 = rna_tf32(v1);
                v2 = rna_tf32(v2); v3 = rna_tf32(v3);
            }
            if (r0 < M)
                *(float2*)(C + (size_t)r0 * N + n0 + cc) = make_float2(v0, v1);
            if (r0 + 8 < M)
                *(float2*)(C + (size_t)(r0 + 8) * N + n0 + cc) = make_float2(v2, v3);
        }
    }
}

// ---------------- K2: adjacency mix + relu + BN partial stats ----------------
__global__ __launch_bounds__(256) void k_adj(const float* __restrict__ adj) {
    __shared__ float sadj[17 * 17];
    int f = blockIdx.x;
    int o = threadIdx.x;
    for (int i = o; i < 289; i += 256) sadj[i] = adj[i];
    __syncthreads();
    const float* tp = g_t + (size_t)f * 17 * 256 + o;
    float v[17];
#pragma unroll
    for (int j = 0; j < 17; j++) v[j] = tp[(size_t)j * 256];
    float* hp = g_h + (size_t)f * 17 * 256 + o;
    float s = 0.f, s2 = 0.f;
#pragma unroll
    for (int i = 0; i < 17; i++) {
        float g = 0.f;
#pragma unroll
        for (int j = 0; j < 17; j++) g = fmaf(sadj[i * 17 + j], v[j], g);
        g = fmaxf(g, 0.f);
        hp[(size_t)i * 256] = g;
        s += g;
        s2 = fmaf(g, g, s2);
    }
    float* st = g_stats + (size_t)(blockIdx.x & (NCOPY - 1)) * 512;
    atomicAdd(st + o, s);
    atomicAdd(st + 256 + o, s2);
}

// ---------------- K3: finalize BN statistics ---------------------------------
__global__ __launch_bounds__(256) void k_finstats(const float* __restrict__ bg,
                                                  const float* __restrict__ bb) {
    int o = threadIdx.x;
    float s = 0.f, s2 = 0.f;
#pragma unroll 8
    for (int c = 0; c < NCOPY; c++) {
        s += g_stats[c * 512 + o];
        s2 += g_stats[c * 512 + 256 + o];
    }
    const float inv = 1.f / (float)R_ROWS;
    float mu = s * inv;
    float var = fmaxf(s2 * inv - mu * mu, 0.f);
    float rs = rsqrtf(var + 1e-5f);
    float sc = rs * bg[o];
    g_sc[o] = sc;
    g_tsh[o] = bb[o] - mu * sc;
}

// ---------------- K4: BN apply + LayerNorm -> hn (tf32-rounded) in g_t -------
__global__ __launch_bounds__(256) void k_bnln(const float* __restrict__ lg,
                                              const float* __restrict__ lb) {
    int row = blockIdx.x * 8 + (threadIdx.x >> 5);
    int lane = threadIdx.x & 31;
    const float* hp = g_h + (size_t)row * 256;
    float v[8];
    float s = 0.f, s2 = 0.f;
#pragma unroll
    for (int i = 0; i < 8; i++) {
        int k = lane + 32 * i;
        float x = fmaf(hp[k], g_sc[k], g_tsh[k]);
        v[i] = x;
        s += x;
        s2 = fmaf(x, x, s2);
    }
#pragma unroll
    for (int off = 16; off; off >>= 1) {
        s += __shfl_xor_sync(0xffffffffu, s, off);
        s2 += __shfl_xor_sync(0xffffffffu, s2, off);
    }
    float mu = s * (1.f / 256.f);
    float var = fmaxf(s2 * (1.f / 256.f) - mu * mu, 0.f);
    float rs = rsqrtf(var + 1e-5f);
    float* op = g_t + (size_t)row * 256;
#pragma unroll
    for (int i = 0; i < 8; i++) {
        int k = lane + 32 * i;
        op[k] = rna_tf32(fmaf((v[i] - mu) * rs, lg[k], lb[k]));
    }
}

// ---------------- host side --------------------------------------------------
#define SMEM_DYN (4 * ABUF)   // 73728 B

extern "C" void kernel_launch(void* const* d_in, const int* in_sizes, int n_in,
                              void* d_out, int out_size) {
    (void)in_sizes; (void)n_in; (void)out_size;
    const float* x   = (const float*)d_in[0];
    const float* adj = (const float*)d_in[1];
    const float* w1  = (const float*)d_in[2];
    const float* b1  = (const float*)d_in[3];
    const float* w2  = (const float*)d_in[4];
    const float* b2  = (const float*)d_in[5];
    const float* bng = (const float*)d_in[6];
    const float* bnb = (const float*)d_in[7];
    const float* lng = (const float*)d_in[8];
    const float* lnb = (const float*)d_in[9];
    const float* mw1 = (const float*)d_in[10];
    const float* mb1 = (const float*)d_in[11];
    const float* mw2 = (const float*)d_in[12];
    const float* mb2 = (const float*)d_in[13];
    float* out = (float*)d_out;

    void *pt = 0, *pm = 0, *pWc = 0, *pW1 = 0, *pW2 = 0, *pbc = 0;
    cudaGetSymbolAddress(&pt, g_t);
    cudaGetSymbolAddress(&pm, g_mid);
    cudaGetSymbolAddress(&pWc, g_Wc);
    cudaGetSymbolAddress(&pW1, g_W1r);
    cudaGetSymbolAddress(&pW2, g_W2r);
    cudaGetSymbolAddress(&pbc, g_bc);

    cudaFuncSetAttribute(k_mma<false, true, false>,
                         cudaFuncAttributeMaxDynamicSharedMemorySize, SMEM_DYN);
    cudaFuncSetAttribute(k_mma<true, false, true>,
                         cudaFuncAttributeMaxDynamicSharedMemorySize, SMEM_DYN);
    cudaFuncSetAttribute(k_mma<false, false, false>,
                         cudaFuncAttributeMaxDynamicSharedMemorySize, SMEM_DYN);

    k_prep<<<512, 256>>>(w1, b1, w2, b2, mw1, mw2);
    // t = x @ Wc^T + bc   (A = raw x -> in-register tf32 round)
    k_mma<false, true, false><<<dim3(2, MTILES), 256, SMEM_DYN>>>(
        x, (const float*)pWc, (const float*)pbc, (float*)pt, R_ROWS, 256, 256);
    // h = relu(adj-mix) + BN partial stats
    k_adj<<<R_ROWS / 17, 256>>>(adj);
    k_finstats<<<1, 256>>>(bng, bnb);
    // hn (tf32-rounded, into g_t) = LN(BN(h))
    k_bnln<<<R_ROWS / 8, 256>>>(lng, lnb);
    // mid = relu(hn @ mlp_w1^T + mb1), tf32-rounded
    k_mma<true, false, true><<<dim3(4, MTILES), 256, SMEM_DYN>>>(
        (const float*)pt, (const float*)pW1, mb1, (float*)pm, R_ROWS, 512, 256);
    // out = mid @ mlp_w2^T + mb2
    k_mma<false, false, false><<<dim3(2, MTILES), 256, SMEM_DYN>>>(
        (const float*)pm, (const float*)pW2, mb2, out, R_ROWS, 256, 512);
}

// round 7
// speedup vs baseline: 2.8187x; 1.0389x over previous
#include <cuda_runtime.h>
#include <cstdint>

#define R_ROWS 264384                    // B*L*J = 64*243*17
#define NCOPY  64                        // striped BN accumulator copies
#define MTILES ((R_ROWS + 127) / 128)    // 2066

// ---------------- scratch (device globals: no allocations allowed) ----------
__device__ float g_t[(long long)R_ROWS * 256];    // t = x@Wc^T + bc, later hn
__device__ float g_h[(long long)R_ROWS * 256];    // h = relu(adj-mix)
__device__ float g_mid[(long long)R_ROWS * 512];  // MLP hidden
__device__ float g_Wc[256 * 256];                 // rna(w1+w2)   [o][d] K-major
__device__ float g_W1r[512 * 256];                // rna(mlp_w1)  [h][o] K-major
__device__ float g_W2r[256 * 512];                // rna(mlp_w2)  [o][h] K-major
__device__ float g_bc[256];                       // b1+b2
__device__ float g_stats[NCOPY * 512];            // [sum(256)|sumsq(256)] per copy
__device__ float g_sc[256];                       // BN scale
__device__ float g_tsh[256];                      // BN shift

// ---------------- helpers ----------------------------------------------------
__device__ __forceinline__ uint32_t smem_u32(const void* p) {
    uint32_t a;
    asm("{ .reg .u64 t; cvta.to.shared.u64 t, %1; cvt.u32.u64 %0, t; }"
        : "=r"(a) : "l"(p));
    return a;
}
__device__ __forceinline__ float rna_tf32(float x) {
    float r;
    asm("cvt.rna.tf32.f32 %0, %1;" : "=f"(r) : "f"(x));
    return r;
}
__device__ __forceinline__ uint32_t rna_tf32_u(uint32_t x) {
    float r;
    asm("cvt.rna.tf32.f32 %0, %1;" : "=f"(r) : "f"(__uint_as_float(x)));
    return __float_as_uint(r);
}
__device__ __forceinline__ void mma_tf32(float* d, const uint32_t* a, const uint32_t* b) {
    asm volatile(
        "mma.sync.aligned.m16n8k8.row.col.f32.tf32.tf32.f32 "
        "{%0,%1,%2,%3}, {%4,%5,%6,%7}, {%8,%9}, {%0,%1,%2,%3};\n"
        : "+f"(d[0]), "+f"(d[1]), "+f"(d[2]), "+f"(d[3])
        : "r"(a[0]), "r"(a[1]), "r"(a[2]), "r"(a[3]), "r"(b[0]), "r"(b[1]));
}
__device__ __forceinline__ void cp16(uint32_t dst, const void* src) {
    asm volatile("cp.async.cg.shared.global [%0], [%1], 16;" :: "r"(dst), "l"(src));
}
__device__ __forceinline__ void cp16z(uint32_t dst, const void* src, unsigned pred16) {
    asm volatile("cp.async.cg.shared.global [%0], [%1], 16, %2;"
                 :: "r"(dst), "l"(src), "r"(pred16));
}

// ---------------- K0: weight prep (tf32-round all GEMM weights) --------------
__global__ __launch_bounds__(256) void k_prep(
        const float* __restrict__ w1, const float* __restrict__ b1,
        const float* __restrict__ w2, const float* __restrict__ b2,
        const float* __restrict__ mw1, const float* __restrict__ mw2) {
    int i = blockIdx.x * 256 + threadIdx.x;   // 0..131071
    g_W1r[i] = rna_tf32(mw1[i]);              // native [512,256] K-major
    g_W2r[i] = rna_tf32(mw2[i]);              // native [256,512] K-major
    if (i < 256 * 256) g_Wc[i] = rna_tf32(w1[i] + w2[i]);
    if (i < NCOPY * 512) g_stats[i] = 0.f;
    if (i < 256) g_bc[i] = b1[i] + b2[i];
}

// ---------- mma.sync tf32 GEMM: C[M,N] = A[M,K] @ Bw[N,K]^T + bias -----------
// CTA 128x256, BK=32, 256 thr (8 warps: 2M x 4N), warp tile 64x64.
// 3-stage cp.async pipeline, one __syncthreads per chunk.
// smem rows padded to 36 floats -> all fragment loads bank-conflict-free.
#define LDA   36
#define ASTG  (128 * LDA * 4)             // 18432 B
#define BSTG  (256 * LDA * 4)             // 36864 B
#define STG   (ASTG + BSTG)               // 55296 B
#define SMEM_DYN (3 * STG)                // 165888 B

template <bool RELU, bool ROUND_A, bool ROUND_OUT>
__global__ __launch_bounds__(256, 1) void k_mma(
        const float* __restrict__ A, const float* __restrict__ Bw,
        const float* __restrict__ bias, float* __restrict__ C,
        int M, int N, int K) {
    extern __shared__ char dsm[];
    __shared__ float s_bias[256];

    const int tid = threadIdx.x;
    const int wid = tid >> 5, lane = tid & 31;
    const int wm = wid >> 2, wn = wid & 3;      // warp grid 2x4
    const int row0 = blockIdx.y * 128;
    const int n0 = blockIdx.x * 256;
    const int NC = K >> 5;

    const uint32_t sb = smem_u32(dsm);
    const uint32_t sA[3] = {sb, sb + STG, sb + 2 * STG};
    const uint32_t sB[3] = {sb + ASTG, sb + STG + ASTG, sb + 2 * STG + ASTG};

    s_bias[tid] = bias[n0 + tid];

    // chunk loader: A 128x32 (1024 16B-segs), B 256x32 (2048 segs)
    auto load_chunk = [&](int ck, int st) {
        const int k0 = ck << 5;
#pragma unroll
        for (int j = 0; j < 4; j++) {
            int id = tid + (j << 8);
            int r = id >> 3, seg = id & 7;
            int gr = row0 + r;
            const float* gp = A + (size_t)(gr < M ? gr : (M - 1)) * K + k0 + (seg << 2);
            cp16z(sA[st] + (uint32_t)(r * LDA + (seg << 2)) * 4u, gp,
                  gr < M ? 16u : 0u);
        }
#pragma unroll
        for (int j = 0; j < 8; j++) {
            int id = tid + (j << 8);
            int r = id >> 3, seg = id & 7;
            const float* gp = Bw + (size_t)(n0 + r) * K + k0 + (seg << 2);
            cp16(sB[st] + (uint32_t)(r * LDA + (seg << 2)) * 4u, gp);
        }
        asm volatile("cp.async.commit_group;" ::: "memory");
    };

    float acc[4][8][4];
#pragma unroll
    for (int i = 0; i < 4; i++)
#pragma unroll
        for (int j = 0; j < 8; j++)
#pragma unroll
            for (int r = 0; r < 4; r++) acc[i][j][r] = 0.f;

    load_chunk(0, 0);
    if (NC > 1) load_chunk(1, 1);

    const int qr = lane >> 2, qc = lane & 3;    // quad row / col
    for (int c = 0; c < NC; c++) {
        if (c + 1 < NC)
            asm volatile("cp.async.wait_group 1;" ::: "memory");
        else
            asm volatile("cp.async.wait_group 0;" ::: "memory");
        __syncthreads();   // chunk c visible to all; all warps done reading c-1

        const int st = c % 3;
        const uint32_t bA = sA[st] + ((wm * 64 + qr) * LDA + qc) * 4u;
        const uint32_t bB = sB[st] + ((wn * 64 + qr) * LDA + qc) * 4u;
#pragma unroll
        for (int s = 0; s < 4; s++) {           // 4 k-steps of 8
            const uint32_t ks = s * 8 * 4u;
            uint32_t af[4][4], bf[8][2];
#pragma unroll
            for (int mt = 0; mt < 4; mt++) {
                uint32_t base = bA + ks + (uint32_t)(mt * 16 * LDA) * 4u;
                asm volatile("ld.shared.b32 %0, [%1];" : "=r"(af[mt][0]) : "r"(base));
                asm volatile("ld.shared.b32 %0, [%1];" : "=r"(af[mt][1]) : "r"(base + 8u * LDA * 4u));
                asm volatile("ld.shared.b32 %0, [%1];" : "=r"(af[mt][2]) : "r"(base + 16u));
                asm volatile("ld.shared.b32 %0, [%1];" : "=r"(af[mt][3]) : "r"(base + 8u * LDA * 4u + 16u));
                if (ROUND_A) {
#pragma unroll
                    for (int r = 0; r < 4; r++) af[mt][r] = rna_tf32_u(af[mt][r]);
                }
            }
#pragma unroll
            for (int nt = 0; nt < 8; nt++) {
                uint32_t base = bB + ks + (uint32_t)(nt * 8 * LDA) * 4u;
                asm volatile("ld.shared.b32 %0, [%1];" : "=r"(bf[nt][0]) : "r"(base));
                asm volatile("ld.shared.b32 %0, [%1];" : "=r"(bf[nt][1]) : "r"(base + 16u));
            }
#pragma unroll
            for (int mt = 0; mt < 4; mt++)
#pragma unroll
                for (int nt = 0; nt < 8; nt++)
                    mma_tf32(acc[mt][nt], af[mt], bf[nt]);
        }
        // prefetch chunk c+2 into the stage just freed (safe: all warps passed
        // this iteration's barrier, i.e. finished reading stage (c-1)%3)
        if (c + 2 < NC) load_chunk(c + 2, (c + 2) % 3);
    }

    // epilogue: bias (+relu) (+tf32 round), float2 stores
#pragma unroll
    for (int mt = 0; mt < 4; mt++) {
        int r0 = row0 + wm * 64 + mt * 16 + qr;
#pragma unroll
        for (int nt = 0; nt < 8; nt++) {
            int cc = wn * 64 + nt * 8 + qc * 2;
            float b0 = s_bias[cc], b1 = s_bias[cc + 1];
            float v0 = acc[mt][nt][0] + b0, v1 = acc[mt][nt][1] + b1;
            float v2 = acc[mt][nt][2] + b0, v3 = acc[mt][nt][3] + b1;
            if (RELU) {
                v0 = fmaxf(v0, 0.f); v1 = fmaxf(v1, 0.f);
                v2 = fmaxf(v2, 0.f); v3 = fmaxf(v3, 0.f);
            }
            if (ROUND_OUT) {
                v0 = rna_tf32(v0); v1 = rna_tf32(v1);
                v2 = rna_tf32(v2); v3 = rna_tf32(v3);
            }
            if (r0 < M)
                *(float2*)(C + (size_t)r0 * N + n0 + cc) = make_float2(v0, v1);
            if (r0 + 8 < M)
                *(float2*)(C + (size_t)(r0 + 8) * N + n0 + cc) = make_float2(v2, v3);
        }
    }
}

// ---------------- K2: adjacency mix + relu + BN partial stats ----------------
__global__ __launch_bounds__(256) void k_adj(const float* __restrict__ adj) {
    __shared__ float sadj[17 * 17];
    int f = blockIdx.x;
    int o = threadIdx.x;
    for (int i = o; i < 289; i += 256) sadj[i] = adj[i];
    __syncthreads();
    const float* tp = g_t + (size_t)f * 17 * 256 + o;
    float v[17];
#pragma unroll
    for (int j = 0; j < 17; j++) v[j] = tp[(size_t)j * 256];
    float* hp = g_h + (size_t)f * 17 * 256 + o;
    float s = 0.f, s2 = 0.f;
#pragma unroll
    for (int i = 0; i < 17; i++) {
        float g = 0.f;
#pragma unroll
        for (int j = 0; j < 17; j++) g = fmaf(sadj[i * 17 + j], v[j], g);
        g = fmaxf(g, 0.f);
        hp[(size_t)i * 256] = g;
        s += g;
        s2 = fmaf(g, g, s2);
    }
    float* st = g_stats + (size_t)(blockIdx.x & (NCOPY - 1)) * 512;
    atomicAdd(st + o, s);
    atomicAdd(st + 256 + o, s2);
}

// ---------------- K3: finalize BN statistics ---------------------------------
__global__ __launch_bounds__(256) void k_finstats(const float* __restrict__ bg,
                                                  const float* __restrict__ bb) {
    int o = threadIdx.x;
    float s = 0.f, s2 = 0.f;
#pragma unroll 8
    for (int c = 0; c < NCOPY; c++) {
        s += g_stats[c * 512 + o];
        s2 += g_stats[c * 512 + 256 + o];
    }
    const float inv = 1.f / (float)R_ROWS;
    float mu = s * inv;
    float var = fmaxf(s2 * inv - mu * mu, 0.f);
    float rs = rsqrtf(var + 1e-5f);
    float sc = rs * bg[o];
    g_sc[o] = sc;
    g_tsh[o] = bb[o] - mu * sc;
}

// ---------------- K4: BN apply + LayerNorm -> hn (tf32-rounded) in g_t -------
__global__ __launch_bounds__(256) void k_bnln(const float* __restrict__ lg,
                                              const float* __restrict__ lb) {
    int row = blockIdx.x * 8 + (threadIdx.x >> 5);
    int lane = threadIdx.x & 31;
    const float* hp = g_h + (size_t)row * 256;
    float v[8];
    float s = 0.f, s2 = 0.f;
#pragma unroll
    for (int i = 0; i < 8; i++) {
        int k = lane + 32 * i;
        float x = fmaf(hp[k], g_sc[k], g_tsh[k]);
        v[i] = x;
        s += x;
        s2 = fmaf(x, x, s2);
    }
#pragma unroll
    for (int off = 16; off; off >>= 1) {
        s += __shfl_xor_sync(0xffffffffu, s, off);
        s2 += __shfl_xor_sync(0xffffffffu, s2, off);
    }
    float mu = s * (1.f / 256.f);
    float var = fmaxf(s2 * (1.f / 256.f) - mu * mu, 0.f);
    float rs = rsqrtf(var + 1e-5f);
    float* op = g_t + (size_t)row * 256;
#pragma unroll
    for (int i = 0; i < 8; i++) {
        int k = lane + 32 * i;
        op[k] = rna_tf32(fmaf((v[i] - mu) * rs, lg[k], lb[k]));
    }
}

// ---------------- host side --------------------------------------------------
extern "C" void kernel_launch(void* const* d_in, const int* in_sizes, int n_in,
                              void* d_out, int out_size) {
    (void)in_sizes; (void)n_in; (void)out_size;
    const float* x   = (const float*)d_in[0];
    const float* adj = (const float*)d_in[1];
    const float* w1  = (const float*)d_in[2];
    const float* b1  = (const float*)d_in[3];
    const float* w2  = (const float*)d_in[4];
    const float* b2  = (const float*)d_in[5];
    const float* bng = (const float*)d_in[6];
    const float* bnb = (const float*)d_in[7];
    const float* lng = (const float*)d_in[8];
    const float* lnb = (const float*)d_in[9];
    const float* mw1 = (const float*)d_in[10];
    const float* mb1 = (const float*)d_in[11];
    const float* mw2 = (const float*)d_in[12];
    const float* mb2 = (const float*)d_in[13];
    float* out = (float*)d_out;

    void *pt = 0, *pm = 0, *pWc = 0, *pW1 = 0, *pW2 = 0, *pbc = 0;
    cudaGetSymbolAddress(&pt, g_t);
    cudaGetSymbolAddress(&pm, g_mid);
    cudaGetSymbolAddress(&pWc, g_Wc);
    cudaGetSymbolAddress(&pW1, g_W1r);
    cudaGetSymbolAddress(&pW2, g_W2r);
    cudaGetSymbolAddress(&pbc, g_bc);

    cudaFuncSetAttribute(k_mma<false, true, false>,
                         cudaFuncAttributeMaxDynamicSharedMemorySize, SMEM_DYN);
    cudaFuncSetAttribute(k_mma<true, false, true>,
                         cudaFuncAttributeMaxDynamicSharedMemorySize, SMEM_DYN);
    cudaFuncSetAttribute(k_mma<false, false, false>,
                         cudaFuncAttributeMaxDynamicSharedMemorySize, SMEM_DYN);

    k_prep<<<512, 256>>>(w1, b1, w2, b2, mw1, mw2);
    // t = x @ Wc^T + bc   (A = raw x -> in-register tf32 round)
    k_mma<false, true, false><<<dim3(1, MTILES), 256, SMEM_DYN>>>(
        x, (const float*)pWc, (const float*)pbc, (float*)pt, R_ROWS, 256, 256);
    // h = relu(adj-mix) + BN partial stats
    k_adj<<<R_ROWS / 17, 256>>>(adj);
    k_finstats<<<1, 256>>>(bng, bnb);
    // hn (tf32-rounded, into g_t) = LN(BN(h))
    k_bnln<<<R_ROWS / 8, 256>>>(lng, lnb);
    // mid = relu(hn @ mlp_w1^T + mb1), tf32-rounded
    k_mma<true, false, true><<<dim3(2, MTILES), 256, SMEM_DYN>>>(
        (const float*)pt, (const float*)pW1, mb1, (float*)pm, R_ROWS, 512, 256);
    // out = mid @ mlp_w2^T + mb2
    k_mma<false, false, false><<<dim3(1, MTILES), 256, SMEM_DYN>>>(
        (const float*)pm, (const float*)pW2, mb2, out, R_ROWS, 256, 512);
}

// round 8
// speedup vs baseline: 3.9394x; 1.3976x over previous
#include <cuda_runtime.h>
#include <cuda_fp16.h>
#include <cstdint>

#define R_ROWS 264384                    // B*L*J = 64*243*17
#define NCOPY  64                        // striped BN accumulator copies
#define MTILES ((R_ROWS + 127) / 128)    // 2066

// ---------------- scratch (device globals: no allocations allowed) ----------
__device__ float  g_t[(long long)R_ROWS * 256];     // t = x@Wc^T + bc (fp32)
__device__ float  g_h[(long long)R_ROWS * 256];     // h = relu(adj-mix) (fp32)
__device__ __half g_hn[(long long)R_ROWS * 256];    // LN output (half)
__device__ __half g_midh[(long long)R_ROWS * 512];  // MLP hidden (half)
__device__ __half g_x16[(long long)R_ROWS * 256];   // x converted to half
__device__ __half g_Wch[256 * 256];                 // h(w1+w2)   [o][d] K-major
__device__ __half g_W1h[512 * 256];                 // h(mlp_w1)  [h][o] K-major
__device__ __half g_W2h[256 * 512];                 // h(mlp_w2)  [o][h] K-major
__device__ float  g_bc[256];                        // b1+b2
__device__ float  g_stats[NCOPY * 512];             // [sum|sumsq] per copy
__device__ float  g_sc[256];                        // BN scale
__device__ float  g_tsh[256];                       // BN shift

// ---------------- helpers ----------------------------------------------------
__device__ __forceinline__ uint32_t smem_u32(const void* p) {
    uint32_t a;
    asm("{ .reg .u64 t; cvta.to.shared.u64 t, %1; cvt.u32.u64 %0, t; }"
        : "=r"(a) : "l"(p));
    return a;
}
__device__ __forceinline__ void mma_f16(float* d, const uint32_t* a, const uint32_t* b) {
    asm volatile(
        "mma.sync.aligned.m16n8k16.row.col.f32.f16.f16.f32 "
        "{%0,%1,%2,%3}, {%4,%5,%6,%7}, {%8,%9}, {%0,%1,%2,%3};\n"
        : "+f"(d[0]), "+f"(d[1]), "+f"(d[2]), "+f"(d[3])
        : "r"(a[0]), "r"(a[1]), "r"(a[2]), "r"(a[3]), "r"(b[0]), "r"(b[1]));
}
__device__ __forceinline__ void cp16(uint32_t dst, const void* src) {
    asm volatile("cp.async.cg.shared.global [%0], [%1], 16;" :: "r"(dst), "l"(src));
}
__device__ __forceinline__ void cp16z(uint32_t dst, const void* src, unsigned pred16) {
    asm volatile("cp.async.cg.shared.global [%0], [%1], 16, %2;"
                 :: "r"(dst), "l"(src), "r"(pred16));
}

// ---------------- K0: weight prep (half) + stats zeroing ---------------------
__global__ __launch_bounds__(256) void k_prep(
        const float* __restrict__ w1, const float* __restrict__ b1,
        const float* __restrict__ w2, const float* __restrict__ b2,
        const float* __restrict__ mw1, const float* __restrict__ mw2) {
    int i = blockIdx.x * 256 + threadIdx.x;   // 0..131071
    g_W1h[i] = __float2half_rn(mw1[i]);       // native [512,256] K-major
    g_W2h[i] = __float2half_rn(mw2[i]);       // native [256,512] K-major
    if (i < 256 * 256) g_Wch[i] = __float2half_rn(w1[i] + w2[i]);
    if (i < NCOPY * 512) g_stats[i] = 0.f;
    if (i < 256) g_bc[i] = b1[i] + b2[i];
}

// ---------------- K0b: x (fp32) -> g_x16 (half), 4 elems/thread --------------
__global__ __launch_bounds__(256) void k_x16(const float* __restrict__ x) {
    long long i = (long long)blockIdx.x * 256 + threadIdx.x;   // float4 index
    float4 v = ((const float4*)x)[i];
    ((__half2*)g_x16)[2 * i] = __floats2half2_rn(v.x, v.y);
    ((__half2*)g_x16)[2 * i + 1] = __floats2half2_rn(v.z, v.w);
}

// ---------- fp16 mma GEMM: C[M,N] = A[M,K] @ Bw[N,K]^T + bias ----------------
// CTA 128x256, BK=32 (2 k16-steps), 256 thr (8 warps: 2M x 4N), warp 64x64.
// 4-stage cp.async pipeline, one __syncthreads per chunk.
// smem rows = 40 halves (80B) -> half2 fragment loads conflict-free.
#define LDH   40
#define ASTG  (128 * LDH * 2)             // 10240 B
#define BSTG  (256 * LDH * 2)             // 20480 B
#define STG   (ASTG + BSTG)               // 30720 B
#define SMEM_DYN (4 * STG)                // 122880 B

template <bool RELU, bool OUT_HALF>
__global__ __launch_bounds__(256, 1) void k_mma(
        const __half* __restrict__ A, const __half* __restrict__ Bw,
        const float* __restrict__ bias, void* __restrict__ Cv,
        int M, int N, int K) {
    extern __shared__ char dsm[];
    __shared__ float s_bias[256];

    const int tid = threadIdx.x;
    const int wid = tid >> 5, lane = tid & 31;
    const int wm = wid >> 2, wn = wid & 3;      // warp grid 2x4
    const int row0 = blockIdx.y * 128;
    const int n0 = blockIdx.x * 256;
    const int NC = K >> 5;

    const uint32_t sb = smem_u32(dsm);

    s_bias[tid] = bias[n0 + tid];

    // chunk loader: A 128 rows x 32 halves (4 x 16B segs), B 256 rows x 4 segs
    auto load_chunk = [&](int ck, int st) {
        const int k0 = ck << 5;
        const uint32_t sA = sb + (uint32_t)st * STG;
        const uint32_t sB = sA + ASTG;
#pragma unroll
        for (int j = 0; j < 2; j++) {           // 512 segs
            int id = tid + (j << 8);
            int r = id >> 2, seg = id & 3;
            int gr = row0 + r;
            const __half* gp =
                A + (size_t)(gr < M ? gr : (M - 1)) * K + k0 + (seg << 3);
            cp16z(sA + (uint32_t)(r * LDH + (seg << 3)) * 2u, gp,
                  gr < M ? 16u : 0u);
        }
#pragma unroll
        for (int j = 0; j < 4; j++) {           // 1024 segs
            int id = tid + (j << 8);
            int r = id >> 2, seg = id & 3;
            const __half* gp = Bw + (size_t)(n0 + r) * K + k0 + (seg << 3);
            cp16(sB + (uint32_t)(r * LDH + (seg << 3)) * 2u, gp);
        }
        asm volatile("cp.async.commit_group;" ::: "memory");
    };

    float acc[4][8][4];
#pragma unroll
    for (int i = 0; i < 4; i++)
#pragma unroll
        for (int j = 0; j < 8; j++)
#pragma unroll
            for (int r = 0; r < 4; r++) acc[i][j][r] = 0.f;

    load_chunk(0, 0);
    load_chunk(1, 1);
    load_chunk(2, 2);

    const int qr = lane >> 2, qc = lane & 3;    // quad row / col
    for (int c = 0; c < NC; c++) {
        if (c + 2 < NC)
            asm volatile("cp.async.wait_group 2;" ::: "memory");
        else if (c + 1 < NC)
            asm volatile("cp.async.wait_group 1;" ::: "memory");
        else
            asm volatile("cp.async.wait_group 0;" ::: "memory");
        __syncthreads();   // chunk c visible; all warps done reading c-1

        const int st = c & 3;
        const uint32_t bA = sb + st * STG + ((wm * 64 + qr) * LDH) * 2u + qc * 4u;
        const uint32_t bB = sb + st * STG + ASTG
                          + ((wn * 64 + qr) * LDH) * 2u + qc * 4u;
#pragma unroll
        for (int s = 0; s < 2; s++) {           // 2 k-steps of 16
            const uint32_t ks = s * 32u;        // 16 halves
            uint32_t af[4][4], bf[8][2];
#pragma unroll
            for (int mt = 0; mt < 4; mt++) {
                uint32_t base = bA + ks + (uint32_t)(mt * 16 * LDH) * 2u;
                asm volatile("ld.shared.b32 %0, [%1];" : "=r"(af[mt][0]) : "r"(base));
                asm volatile("ld.shared.b32 %0, [%1];" : "=r"(af[mt][1]) : "r"(base + 8u * LDH * 2u));
                asm volatile("ld.shared.b32 %0, [%1];" : "=r"(af[mt][2]) : "r"(base + 16u));
                asm volatile("ld.shared.b32 %0, [%1];" : "=r"(af[mt][3]) : "r"(base + 8u * LDH * 2u + 16u));
            }
#pragma unroll
            for (int nt = 0; nt < 8; nt++) {
                uint32_t base = bB + ks + (uint32_t)(nt * 8 * LDH) * 2u;
                asm volatile("ld.shared.b32 %0, [%1];" : "=r"(bf[nt][0]) : "r"(base));
                asm volatile("ld.shared.b32 %0, [%1];" : "=r"(bf[nt][1]) : "r"(base + 16u));
            }
#pragma unroll
            for (int mt = 0; mt < 4; mt++)
#pragma unroll
                for (int nt = 0; nt < 8; nt++)
                    mma_f16(acc[mt][nt], af[mt], bf[nt]);
        }
        // prefetch chunk c+3 into the freed stage ((c+3)&3 == (c-1)&3)
        if (c + 3 < NC) load_chunk(c + 3, (c + 3) & 3);
    }

    // epilogue: bias (+relu), fp32 or half stores
#pragma unroll
    for (int mt = 0; mt < 4; mt++) {
        int r0 = row0 + wm * 64 + mt * 16 + qr;
#pragma unroll
        for (int nt = 0; nt < 8; nt++) {
            int cc = wn * 64 + nt * 8 + qc * 2;
            float b0 = s_bias[cc], b1 = s_bias[cc + 1];
            float v0 = acc[mt][nt][0] + b0, v1 = acc[mt][nt][1] + b1;
            float v2 = acc[mt][nt][2] + b0, v3 = acc[mt][nt][3] + b1;
            if (RELU) {
                v0 = fmaxf(v0, 0.f); v1 = fmaxf(v1, 0.f);
                v2 = fmaxf(v2, 0.f); v3 = fmaxf(v3, 0.f);
            }
            if (OUT_HALF) {
                __half* C = (__half*)Cv;
                if (r0 < M)
                    *(__half2*)(C + (size_t)r0 * N + n0 + cc) = __floats2half2_rn(v0, v1);
                if (r0 + 8 < M)
                    *(__half2*)(C + (size_t)(r0 + 8) * N + n0 + cc) = __floats2half2_rn(v2, v3);
            } else {
                float* C = (float*)Cv;
                if (r0 < M)
                    *(float2*)(C + (size_t)r0 * N + n0 + cc) = make_float2(v0, v1);
                if (r0 + 8 < M)
                    *(float2*)(C + (size_t)(r0 + 8) * N + n0 + cc) = make_float2(v2, v3);
            }
        }
    }
}

// ---------------- K2: adjacency mix + relu + BN partial stats ----------------
__global__ __launch_bounds__(256) void k_adj(const float* __restrict__ adj) {
    __shared__ float sadj[17 * 17];
    int f = blockIdx.x;
    int o = threadIdx.x;
    for (int i = o; i < 289; i += 256) sadj[i] = adj[i];
    __syncthreads();
    const float* tp = g_t + (size_t)f * 17 * 256 + o;
    float v[17];
#pragma unroll
    for (int j = 0; j < 17; j++) v[j] = tp[(size_t)j * 256];
    float* hp = g_h + (size_t)f * 17 * 256 + o;
    float s = 0.f, s2 = 0.f;
#pragma unroll
    for (int i = 0; i < 17; i++) {
        float g = 0.f;
#pragma unroll
        for (int j = 0; j < 17; j++) g = fmaf(sadj[i * 17 + j], v[j], g);
        g = fmaxf(g, 0.f);
        hp[(size_t)i * 256] = g;
        s += g;
        s2 = fmaf(g, g, s2);
    }
    float* st = g_stats + (size_t)(blockIdx.x & (NCOPY - 1)) * 512;
    atomicAdd(st + o, s);
    atomicAdd(st + 256 + o, s2);
}

// ---------------- K3: finalize BN statistics ---------------------------------
__global__ __launch_bounds__(256) void k_finstats(const float* __restrict__ bg,
                                                  const float* __restrict__ bb) {
    int o = threadIdx.x;
    float s = 0.f, s2 = 0.f;
#pragma unroll 8
    for (int c = 0; c < NCOPY; c++) {
        s += g_stats[c * 512 + o];
        s2 += g_stats[c * 512 + 256 + o];
    }
    const float inv = 1.f / (float)R_ROWS;
    float mu = s * inv;
    float var = fmaxf(s2 * inv - mu * mu, 0.f);
    float rs = rsqrtf(var + 1e-5f);
    float sc = rs * bg[o];
    g_sc[o] = sc;
    g_tsh[o] = bb[o] - mu * sc;
}

// ---------------- K4: BN apply + LayerNorm -> hn (half) ----------------------
__global__ __launch_bounds__(256) void k_bnln(const float* __restrict__ lg,
                                              const float* __restrict__ lb) {
    int row = blockIdx.x * 8 + (threadIdx.x >> 5);
    int lane = threadIdx.x & 31;
    const float* hp = g_h + (size_t)row * 256;
    float v[8];
    float s = 0.f, s2 = 0.f;
#pragma unroll
    for (int i = 0; i < 8; i++) {
        int k = lane + 32 * i;
        float x = fmaf(hp[k], g_sc[k], g_tsh[k]);
        v[i] = x;
        s += x;
        s2 = fmaf(x, x, s2);
    }
#pragma unroll
    for (int off = 16; off; off >>= 1) {
        s += __shfl_xor_sync(0xffffffffu, s, off);
        s2 += __shfl_xor_sync(0xffffffffu, s2, off);
    }
    float mu = s * (1.f / 256.f);
    float var = fmaxf(s2 * (1.f / 256.f) - mu * mu, 0.f);
    float rs = rsqrtf(var + 1e-5f);
    __half* op = g_hn + (size_t)row * 256;
#pragma unroll
    for (int i = 0; i < 8; i++) {
        int k = lane + 32 * i;
        op[k] = __float2half_rn(fmaf((v[i] - mu) * rs, lg[k], lb[k]));
    }
}

// ---------------- host side --------------------------------------------------
extern "C" void kernel_launch(void* const* d_in, const int* in_sizes, int n_in,
                              void* d_out, int out_size) {
    (void)in_sizes; (void)n_in; (void)out_size;
    const float* x   = (const float*)d_in[0];
    const float* adj = (const float*)d_in[1];
    const float* w1  = (const float*)d_in[2];
    const float* b1  = (const float*)d_in[3];
    const float* w2  = (const float*)d_in[4];
    const float* b2  = (const float*)d_in[5];
    const float* bng = (const float*)d_in[6];
    const float* bnb = (const float*)d_in[7];
    const float* lng = (const float*)d_in[8];
    const float* lnb = (const float*)d_in[9];
    const float* mw1 = (const float*)d_in[10];
    const float* mb1 = (const float*)d_in[11];
    const float* mw2 = (const float*)d_in[12];
    const float* mb2 = (const float*)d_in[13];
    float* out = (float*)d_out;

    void *pt = 0, *px = 0, *phn = 0, *pm = 0, *pWc = 0, *pW1 = 0, *pW2 = 0, *pbc = 0;
    cudaGetSymbolAddress(&pt, g_t);
    cudaGetSymbolAddress(&px, g_x16);
    cudaGetSymbolAddress(&phn, g_hn);
    cudaGetSymbolAddress(&pm, g_midh);
    cudaGetSymbolAddress(&pWc, g_Wch);
    cudaGetSymbolAddress(&pW1, g_W1h);
    cudaGetSymbolAddress(&pW2, g_W2h);
    cudaGetSymbolAddress(&pbc, g_bc);

    cudaFuncSetAttribute(k_mma<false, false>,
                         cudaFuncAttributeMaxDynamicSharedMemorySize, SMEM_DYN);
    cudaFuncSetAttribute(k_mma<true, true>,
                         cudaFuncAttributeMaxDynamicSharedMemorySize, SMEM_DYN);

    k_prep<<<512, 256>>>(w1, b1, w2, b2, mw1, mw2);
    k_x16<<<(R_ROWS * 256 / 4) / 256, 256>>>(x);
    // t = x16 @ Wc^T + bc  (fp32 out)
    k_mma<false, false><<<dim3(1, MTILES), 256, SMEM_DYN>>>(
        (const __half*)px, (const __half*)pWc, (const float*)pbc,
        (float*)pt, R_ROWS, 256, 256);
    // h = relu(adj-mix) + BN partial stats
    k_adj<<<R_ROWS / 17, 256>>>(adj);
    k_finstats<<<1, 256>>>(bng, bnb);
    // hn (half) = LN(BN(h))
    k_bnln<<<R_ROWS / 8, 256>>>(lng, lnb);
    // mid (half) = relu(hn @ mlp_w1^T + mb1)
    k_mma<true, true><<<dim3(2, MTILES), 256, SMEM_DYN>>>(
        (const __half*)phn, (const __half*)pW1, mb1, (void*)pm, R_ROWS, 512, 256);
    // out (fp32) = mid @ mlp_w2^T + mb2
    k_mma<false, false><<<dim3(1, MTILES), 256, SMEM_DYN>>>(
        (const __half*)pm, (const __half*)pW2, mb2, (void*)out, R_ROWS, 256, 512);
}